// round 3
// baseline (speedup 1.0000x reference)
#include <cuda_runtime.h>
#include <cuda_bf16.h>
#include <cstdint>

// ============================================================================
// Problem constants: B=64, K=24, D=8, n=64 obj, 4096 pairs/batch, IN=52
// ============================================================================
static constexpr int NB   = 64;
static constexpr int NOBJ = 64;
static constexpr int HID  = 256;
static constexpr int NOUT = 28;

// ============================================================================
// PTX helpers: ldmatrix + mma.sync (sm_80-era, valid on plain sm_100 target)
// ============================================================================
__device__ __forceinline__ uint32_t smem_to_u32(const void* smem_ptr) {
    uint32_t addr;
    asm("{ .reg .u64 tmp; cvta.to.shared.u64 tmp, %1; cvt.u32.u64 %0, tmp; }"
        : "=r"(addr) : "l"(smem_ptr));
    return addr;
}

#define LDSM_X4(r0, r1, r2, r3, addr) \
    asm volatile("ldmatrix.sync.aligned.m8n8.x4.shared.b16 {%0,%1,%2,%3}, [%4];" \
                 : "=r"(r0), "=r"(r1), "=r"(r2), "=r"(r3) : "r"(addr))

#define LDSM_X2(r0, r1, addr) \
    asm volatile("ldmatrix.sync.aligned.m8n8.x2.shared.b16 {%0,%1}, [%2];" \
                 : "=r"(r0), "=r"(r1) : "r"(addr))

#define MMA16816(d0, d1, d2, d3, a0, a1, a2, a3, b0, b1) \
    asm volatile("mma.sync.aligned.m16n8k16.row.col.f32.bf16.bf16.f32 " \
                 "{%0,%1,%2,%3}, {%4,%5,%6,%7}, {%8,%9}, {%0,%1,%2,%3};" \
                 : "+f"(d0), "+f"(d1), "+f"(d2), "+f"(d3) \
                 : "r"(a0), "r"(a1), "r"(a2), "r"(a3), "r"(b0), "r"(b1))

// ============================================================================
// Device-global scratch (no dynamic allocation allowed)
// ============================================================================
__device__ __align__(16) float g_A[NB * NOBJ * HID];
__device__ __align__(16) float g_C[NB * NOBJ * HID];
__device__ __align__(16) float g_qbias[NB * HID];
__device__ float g_xg[NB * HID];
__device__ __align__(16) __nv_bfloat16 g_Wbf[4 * HID * HID];

// ============================================================================
// K0: zero x_g accumulator
// ============================================================================
__global__ void k_zero() {
    g_xg[blockIdx.x * 256 + threadIdx.x] = 0.0f;
}

// ============================================================================
// K1: A[b,q,o] = Wg1[o,:26].feat[b,q],  C[b,p,o] = Wg1[o,26:].feat[b,p]
// feat: 24 x-channels + cx(coords[col]) + cy(coords[row]); coords=linspace(-4,4,8)
// ============================================================================
__global__ void k_precompute_AC(const float* __restrict__ x,
                                const float* __restrict__ Wg1) {
    __shared__ float feat[NOBJ][26];
    int b = blockIdx.x;
    int t = threadIdx.x;   // 256

    for (int idx = t; idx < NOBJ * 26; idx += 256) {
        int j = idx / 26, i = idx % 26;
        int r = j >> 3, c = j & 7;
        float v;
        if (i < 24)       v = x[((b * 24 + i) * 8 + r) * 8 + c];
        else if (i == 24) v = c * (8.0f / 7.0f) - 4.0f;
        else              v = r * (8.0f / 7.0f) - 4.0f;
        feat[j][i] = v;
    }
    __syncthreads();

    int o = t;
    float wA[26], wC[26];
#pragma unroll
    for (int i = 0; i < 26; i++) {
        wA[i] = Wg1[o * 52 + i];
        wC[i] = Wg1[o * 52 + 26 + i];
    }
    for (int j = 0; j < NOBJ; j++) {
        float sa = 0.0f, sc = 0.0f;
#pragma unroll
        for (int i = 0; i < 26; i++) {
            float f = feat[j][i];
            sa += wA[i] * f;
            sc += wC[i] * f;
        }
        g_A[(b * NOBJ + j) * HID + o] = sa;
        g_C[(b * NOBJ + j) * HID + o] = sc;
    }
}

// ============================================================================
// K2: qbias[b,o] = bh1[o] + Wh1[o, 256:].qst[b]
// ============================================================================
__global__ void k_qbias(const float* __restrict__ qst,
                        const float* __restrict__ Wh1,
                        const float* __restrict__ bh1) {
    __shared__ float qs[256];
    int b = blockIdx.x, o = threadIdx.x;
    qs[o] = qst[b * 256 + o];
    __syncthreads();
    float s = bh1[o];
    const float* wr = Wh1 + o * 512 + 256;
#pragma unroll 8
    for (int i = 0; i < 256; i++) s += wr[i] * qs[i];
    g_qbias[b * 256 + o] = s;
}

// ============================================================================
// K3: Wg2/Wg3/Wg4/Wh1[:, :256] fp32 -> bf16 row-major [256 out][256 K]
// ============================================================================
__global__ void k_convw(const float* __restrict__ Wg2, const float* __restrict__ Wg3,
                        const float* __restrict__ Wg4, const float* __restrict__ Wh1) {
    int idx = blockIdx.x * 256 + threadIdx.x;
    int layer = idx >> 16, e = idx & 65535;
    float v;
    if (layer == 0)      v = Wg2[e];
    else if (layer == 1) v = Wg3[e];
    else if (layer == 2) v = Wg4[e];
    else { int o = e >> 8, i = e & 255; v = Wh1[o * 512 + i]; }
    g_Wbf[idx] = __float2bfloat16(v);
}

// ============================================================================
// K4: fused RN core, HMMA version.
// Grid = 2048 tiles (64 b x 32), 256 threads (8 warps).
// SMEM: act [128 x 264 bf16], W [256 x 264 bf16], bias[256], acc[256].
// Warp tile 64x64: warp_m = wid&1 (rows), warp_n = wid>>1 (cols).
// Layers: 4 x GEMM [128x256]x[256x256] with bias+relu epilogues; last layer
// reduces rows into s_acc, then atomicAdd to g_xg.
// ============================================================================
static constexpr int ACT_STRIDE_H = 264;           // bf16 elems per act row
static constexpr int ACT_STRIDE_B = 528;           // bytes
static constexpr int SMEM_ACT  = 0;
static constexpr int SMEM_WGT  = 128 * ACT_STRIDE_B;            // 67584
static constexpr int SMEM_BIAS = SMEM_WGT + 256 * ACT_STRIDE_B; // 202752
static constexpr int SMEM_RACC = SMEM_BIAS + 1024;              // 203776
static constexpr int SMEM_MAIN_SZ = SMEM_RACC + 1024;           // 204800

__global__ void __launch_bounds__(256, 1)
k_main(const float* __restrict__ bg1, const float* __restrict__ bg2,
       const float* __restrict__ bg3, const float* __restrict__ bg4) {
    extern __shared__ char smem[];
    const uint32_t smem_base = smem_to_u32(smem);

    __nv_bfloat16* s_act = (__nv_bfloat16*)(smem + SMEM_ACT);
    float* s_bias = (float*)(smem + SMEM_BIAS);
    float* s_acc  = (float*)(smem + SMEM_RACC);

    int tid  = threadIdx.x;
    int wid  = tid >> 5;
    int lane = tid & 31;

    int b    = blockIdx.x >> 5;
    int row0 = (blockIdx.x & 31) << 7;   // 128 rows per CTA

    // zero column accumulator
    s_acc[tid] = 0.0f;

    // ---- layer 1: act = relu(A[b,q] + C[b,p] + bg1), bf16 ----
    {
        int r = tid >> 1;                 // 0..127
        int half = tid & 1;               // which 128 cols
        int rowg = row0 + r;
        int p = rowg >> 6, q = rowg & 63;
        const float2* A2 = (const float2*)(g_A + ((b << 6) + q) * HID + half * 128);
        const float2* C2 = (const float2*)(g_C + ((b << 6) + p) * HID + half * 128);
        const float2* B2 = (const float2*)(bg1 + half * 128);
        uint32_t* dst = (uint32_t*)(s_act + r * ACT_STRIDE_H + half * 128);
#pragma unroll
        for (int c = 0; c < 64; c++) {
            float2 av = A2[c], cv = C2[c], bv = B2[c];
            float f0 = fmaxf(av.x + cv.x + bv.x, 0.0f);
            float f1 = fmaxf(av.y + cv.y + bv.y, 0.0f);
            uint32_t lo = (uint32_t)__bfloat16_as_ushort(__float2bfloat16(f0));
            uint32_t hi = (uint32_t)__bfloat16_as_ushort(__float2bfloat16(f1));
            dst[c] = lo | (hi << 16);
        }
    }
    __syncthreads();

    // per-warp tile coordinates
    int warp_m = wid & 1;        // 0..1  -> 64-row group
    int warp_n = wid >> 1;       // 0..3  -> 64-col group
    int mbase = warp_m * 64;
    int nbase = warp_n * 64;

    // per-thread ldmatrix base addresses
    // A (act): 16x16 tiles; lane<16 -> row mbase+mt*16+lane, col 0;
    //          lane>=16 -> row +lane-16, col 8
    uint32_t a_ptr[4];
#pragma unroll
    for (int mt = 0; mt < 4; mt++) {
        int rr = mbase + mt * 16 + (lane & 15);
        a_ptr[mt] = smem_base + SMEM_ACT + rr * ACT_STRIDE_B + (lane >> 4) * 16;
    }
    // B (weights): n8k16 tiles; rows = output channels
    uint32_t b_ptr[8];
#pragma unroll
    for (int nt = 0; nt < 8; nt++) {
        int rr = nbase + nt * 8 + (lane & 7);
        b_ptr[nt] = smem_base + SMEM_WGT + rr * ACT_STRIDE_B + ((lane >> 3) & 1) * 16;
    }

    // ---- layers 2..5 ----
#pragma unroll 1
    for (int L = 0; L < 4; L++) {
        // stage bias
        const float* bp = (L == 0) ? bg2 : (L == 1) ? bg3 : (L == 2) ? bg4
                                         : (const float*)(g_qbias + b * 256);
        if (tid < 256) s_bias[tid] = bp[tid];

        // stage weights [256 x 256] bf16 -> SMEM [256 x 264]
        {
            const uint4* wsrc = (const uint4*)(g_Wbf + L * 65536);
#pragma unroll 8
            for (int idx = tid; idx < 8192; idx += 256) {
                int rowW = idx >> 5;          // 32 x 16B chunks per row
                int koff = (idx & 31) * 16;   // byte offset in row
                *(uint4*)(smem + SMEM_WGT + rowW * ACT_STRIDE_B + koff) = wsrc[idx];
            }
        }
        __syncthreads();

        // mainloop: D[128x256] = act[128x256] @ W^T
        float acc[4][8][4];
#pragma unroll
        for (int mt = 0; mt < 4; mt++)
#pragma unroll
            for (int nt = 0; nt < 8; nt++)
#pragma unroll
                for (int j = 0; j < 4; j++) acc[mt][nt][j] = 0.0f;

#pragma unroll
        for (int ks = 0; ks < 16; ks++) {
            uint32_t af[4][4];
#pragma unroll
            for (int mt = 0; mt < 4; mt++)
                LDSM_X4(af[mt][0], af[mt][1], af[mt][2], af[mt][3],
                        a_ptr[mt] + ks * 32);
            uint32_t bf[8][2];
#pragma unroll
            for (int nt = 0; nt < 8; nt++)
                LDSM_X2(bf[nt][0], bf[nt][1], b_ptr[nt] + ks * 32);
#pragma unroll
            for (int mt = 0; mt < 4; mt++)
#pragma unroll
                for (int nt = 0; nt < 8; nt++)
                    MMA16816(acc[mt][nt][0], acc[mt][nt][1],
                             acc[mt][nt][2], acc[mt][nt][3],
                             af[mt][0], af[mt][1], af[mt][2], af[mt][3],
                             bf[nt][0], bf[nt][1]);
        }

        __syncthreads();   // all reads of act & W done before overwrite

        if (L < 3) {
            // epilogue: act = bf16(relu(D + bias)), in place
#pragma unroll
            for (int mt = 0; mt < 4; mt++) {
                int r0 = mbase + mt * 16 + (lane >> 2);
#pragma unroll
                for (int nt = 0; nt < 8; nt++) {
                    int c0 = nbase + nt * 8 + (lane & 3) * 2;
                    float bia0 = s_bias[c0], bia1 = s_bias[c0 + 1];
                    float f0 = fmaxf(acc[mt][nt][0] + bia0, 0.0f);
                    float f1 = fmaxf(acc[mt][nt][1] + bia1, 0.0f);
                    float f2 = fmaxf(acc[mt][nt][2] + bia0, 0.0f);
                    float f3 = fmaxf(acc[mt][nt][3] + bia1, 0.0f);
                    uint32_t v01 = (uint32_t)__bfloat16_as_ushort(__float2bfloat16(f0))
                                 | ((uint32_t)__bfloat16_as_ushort(__float2bfloat16(f1)) << 16);
                    uint32_t v23 = (uint32_t)__bfloat16_as_ushort(__float2bfloat16(f2))
                                 | ((uint32_t)__bfloat16_as_ushort(__float2bfloat16(f3)) << 16);
                    *(uint32_t*)(s_act + r0 * ACT_STRIDE_H + c0) = v01;
                    *(uint32_t*)(s_act + (r0 + 8) * ACT_STRIDE_H + c0) = v23;
                }
            }
            __syncthreads();
        } else {
            // final layer: relu(D + qbias), sum over rows -> s_acc
#pragma unroll
            for (int nt = 0; nt < 8; nt++) {
                int c0 = nbase + nt * 8 + (lane & 3) * 2;
                float bia0 = s_bias[c0], bia1 = s_bias[c0 + 1];
                float cs0 = 0.0f, cs1 = 0.0f;
#pragma unroll
                for (int mt = 0; mt < 4; mt++) {
                    cs0 += fmaxf(acc[mt][nt][0] + bia0, 0.0f)
                         + fmaxf(acc[mt][nt][2] + bia0, 0.0f);
                    cs1 += fmaxf(acc[mt][nt][1] + bia1, 0.0f)
                         + fmaxf(acc[mt][nt][3] + bia1, 0.0f);
                }
                // reduce across the 8 lanes sharing (lane & 3)
#pragma unroll
                for (int s = 4; s < 32; s <<= 1) {
                    cs0 += __shfl_xor_sync(0xFFFFFFFF, cs0, s);
                    cs1 += __shfl_xor_sync(0xFFFFFFFF, cs1, s);
                }
                if ((lane >> 2) == 0) {
                    atomicAdd(&s_acc[c0], cs0);
                    atomicAdd(&s_acc[c0 + 1], cs1);
                }
            }
            __syncthreads();
        }
    }

    atomicAdd(&g_xg[b * 256 + tid], s_acc[tid]);
}

// ============================================================================
// K5: f-MLP + log_softmax (tiny). One block of 256 per batch.
// ============================================================================
__global__ void k_final(const float* __restrict__ Wf1, const float* __restrict__ bf1v,
                        const float* __restrict__ Wf2, const float* __restrict__ bf2v,
                        const float* __restrict__ Wf3, const float* __restrict__ bf3v,
                        float* __restrict__ out) {
    __shared__ float s0[256], s1[256], lg[NOUT];
    __shared__ float lse;
    int b = blockIdx.x, t = threadIdx.x;
    s0[t] = g_xg[b * 256 + t];
    __syncthreads();

    float a = bf1v[t];
    const float* w = Wf1 + t * 256;
#pragma unroll 8
    for (int i = 0; i < 256; i++) a += w[i] * s0[i];
    s1[t] = fmaxf(a, 0.0f);
    __syncthreads();

    a = bf2v[t];
    w = Wf2 + t * 256;
#pragma unroll 8
    for (int i = 0; i < 256; i++) a += w[i] * s1[i];
    s0[t] = fmaxf(a, 0.0f);
    __syncthreads();

    if (t < NOUT) {
        a = bf3v[t];
        w = Wf3 + t * 256;
#pragma unroll 8
        for (int i = 0; i < 256; i++) a += w[i] * s0[i];
        lg[t] = a;
    }
    __syncthreads();
    if (t == 0) {
        float m = lg[0];
        for (int i = 1; i < NOUT; i++) m = fmaxf(m, lg[i]);
        float se = 0.0f;
        for (int i = 0; i < NOUT; i++) se += expf(lg[i] - m);
        lse = m + logf(se);
    }
    __syncthreads();
    if (t < NOUT) out[b * NOUT + t] = lg[t] - lse;
}

// ============================================================================
// kernel_launch — inputs in metadata order:
// x, qst, Wg1, bg1, Wg2, bg2, Wg3, bg3, Wg4, bg4, Wh1, bh1,
// Wf1, bf1, Wf2, bf2, Wf3, bf3 ; output float [64, 28]
// ============================================================================
extern "C" void kernel_launch(void* const* d_in, const int* in_sizes, int n_in,
                              void* d_out, int out_size) {
    const float* x    = (const float*)d_in[0];
    const float* qst  = (const float*)d_in[1];
    const float* Wg1  = (const float*)d_in[2];
    const float* bg1  = (const float*)d_in[3];
    const float* Wg2  = (const float*)d_in[4];
    const float* bg2  = (const float*)d_in[5];
    const float* Wg3  = (const float*)d_in[6];
    const float* bg3  = (const float*)d_in[7];
    const float* Wg4  = (const float*)d_in[8];
    const float* bg4  = (const float*)d_in[9];
    const float* Wh1  = (const float*)d_in[10];
    const float* bh1  = (const float*)d_in[11];
    const float* Wf1  = (const float*)d_in[12];
    const float* bf1v = (const float*)d_in[13];
    const float* Wf2  = (const float*)d_in[14];
    const float* bf2v = (const float*)d_in[15];
    const float* Wf3  = (const float*)d_in[16];
    const float* bf3v = (const float*)d_in[17];
    float* out = (float*)d_out;

    static bool attr_set = false;
    if (!attr_set) {
        cudaFuncSetAttribute(k_main, cudaFuncAttributeMaxDynamicSharedMemorySize,
                             SMEM_MAIN_SZ);
        attr_set = true;
    }

    k_zero<<<NB, 256>>>();
    k_precompute_AC<<<NB, 256>>>(x, Wg1);
    k_qbias<<<NB, 256>>>(qst, Wh1, bh1);
    k_convw<<<1024, 256>>>(Wg2, Wg3, Wg4, Wh1);
    k_main<<<2048, 256, SMEM_MAIN_SZ>>>(bg1, bg2, bg3, bg4);
    k_final<<<NB, 256>>>(Wf1, bf1v, Wf2, bf2v, Wf3, bf3v, out);
}

// round 4
// speedup vs baseline: 1.0148x; 1.0148x over previous
#include <cuda_runtime.h>
#include <cuda_bf16.h>
#include <cstdint>

// ============================================================================
// Problem constants: B=64, K=24, D=8, n=64 obj, 4096 pairs/batch, IN=52
// ============================================================================
static constexpr int NB   = 64;
static constexpr int NOBJ = 64;
static constexpr int HID  = 256;
static constexpr int NOUT = 28;

// ============================================================================
// PTX helpers: ldmatrix + mma.sync + cp.async (sm_80-era, valid on sm_100)
// ============================================================================
__device__ __forceinline__ uint32_t smem_to_u32(const void* smem_ptr) {
    uint32_t addr;
    asm("{ .reg .u64 tmp; cvta.to.shared.u64 tmp, %1; cvt.u32.u64 %0, tmp; }"
        : "=r"(addr) : "l"(smem_ptr));
    return addr;
}

#define LDSM_X4(r0, r1, r2, r3, addr) \
    asm volatile("ldmatrix.sync.aligned.m8n8.x4.shared.b16 {%0,%1,%2,%3}, [%4];" \
                 : "=r"(r0), "=r"(r1), "=r"(r2), "=r"(r3) : "r"(addr))

#define LDSM_X2(r0, r1, addr) \
    asm volatile("ldmatrix.sync.aligned.m8n8.x2.shared.b16 {%0,%1}, [%2];" \
                 : "=r"(r0), "=r"(r1) : "r"(addr))

#define MMA16816(d0, d1, d2, d3, a0, a1, a2, a3, b0, b1) \
    asm volatile("mma.sync.aligned.m16n8k16.row.col.f32.bf16.bf16.f32 " \
                 "{%0,%1,%2,%3}, {%4,%5,%6,%7}, {%8,%9}, {%0,%1,%2,%3};" \
                 : "+f"(d0), "+f"(d1), "+f"(d2), "+f"(d3) \
                 : "r"(a0), "r"(a1), "r"(a2), "r"(a3), "r"(b0), "r"(b1))

#define CP_ASYNC16(dst_u32, src_ptr) \
    asm volatile("cp.async.cg.shared.global [%0], [%1], 16;" \
                 :: "r"(dst_u32), "l"(src_ptr))

#define CP_ASYNC_COMMIT() asm volatile("cp.async.commit_group;" ::: "memory")
#define CP_ASYNC_WAIT(n)  asm volatile("cp.async.wait_group %0;" :: "n"(n) : "memory")

// ============================================================================
// Device-global scratch (no dynamic allocation allowed)
// ============================================================================
__device__ __align__(16) float g_A[NB * NOBJ * HID];
__device__ __align__(16) float g_C[NB * NOBJ * HID];
__device__ __align__(16) float g_qbias[NB * HID];
__device__ float g_xg[NB * HID];
// chunked layout: [layer 0..3][chunk 0..1][out 0..255][k 0..127] bf16
__device__ __align__(16) __nv_bfloat16 g_Wbf[4 * HID * HID];

// ============================================================================
// K0: zero x_g accumulator
// ============================================================================
__global__ void k_zero() {
    g_xg[blockIdx.x * 256 + threadIdx.x] = 0.0f;
}

// ============================================================================
// K1: A[b,q,o] = Wg1[o,:26].feat[b,q],  C[b,p,o] = Wg1[o,26:].feat[b,p]
// ============================================================================
__global__ void k_precompute_AC(const float* __restrict__ x,
                                const float* __restrict__ Wg1) {
    __shared__ float feat[NOBJ][26];
    int b = blockIdx.x;
    int t = threadIdx.x;   // 256

    for (int idx = t; idx < NOBJ * 26; idx += 256) {
        int j = idx / 26, i = idx % 26;
        int r = j >> 3, c = j & 7;
        float v;
        if (i < 24)       v = x[((b * 24 + i) * 8 + r) * 8 + c];
        else if (i == 24) v = c * (8.0f / 7.0f) - 4.0f;
        else              v = r * (8.0f / 7.0f) - 4.0f;
        feat[j][i] = v;
    }
    __syncthreads();

    int o = t;
    float wA[26], wC[26];
#pragma unroll
    for (int i = 0; i < 26; i++) {
        wA[i] = Wg1[o * 52 + i];
        wC[i] = Wg1[o * 52 + 26 + i];
    }
    for (int j = 0; j < NOBJ; j++) {
        float sa = 0.0f, sc = 0.0f;
#pragma unroll
        for (int i = 0; i < 26; i++) {
            float f = feat[j][i];
            sa += wA[i] * f;
            sc += wC[i] * f;
        }
        g_A[(b * NOBJ + j) * HID + o] = sa;
        g_C[(b * NOBJ + j) * HID + o] = sc;
    }
}

// ============================================================================
// K2: qbias[b,o] = bh1[o] + Wh1[o, 256:].qst[b]
// ============================================================================
__global__ void k_qbias(const float* __restrict__ qst,
                        const float* __restrict__ Wh1,
                        const float* __restrict__ bh1) {
    __shared__ float qs[256];
    int b = blockIdx.x, o = threadIdx.x;
    qs[o] = qst[b * 256 + o];
    __syncthreads();
    float s = bh1[o];
    const float* wr = Wh1 + o * 512 + 256;
#pragma unroll 8
    for (int i = 0; i < 256; i++) s += wr[i] * qs[i];
    g_qbias[b * 256 + o] = s;
}

// ============================================================================
// K3: weights fp32 -> bf16, chunked layout [L][chunk][out][k128]
// ============================================================================
__global__ void k_convw(const float* __restrict__ Wg2, const float* __restrict__ Wg3,
                        const float* __restrict__ Wg4, const float* __restrict__ Wh1) {
    int idx = blockIdx.x * 256 + threadIdx.x;   // 0 .. 4*65536-1
    int layer = idx >> 16, e = idx & 65535;
    int o = e >> 8, i = e & 255;
    float v;
    if (layer == 0)      v = Wg2[e];
    else if (layer == 1) v = Wg3[e];
    else if (layer == 2) v = Wg4[e];
    else                 v = Wh1[o * 512 + i];
    int c = i >> 7, k = i & 127;
    g_Wbf[(((layer * 2 + c) * 256 + o) << 7) + k] = __float2bfloat16(v);
}

// ============================================================================
// K4: fused RN core, HMMA + cp.async double-buffered K-chunk staging.
// Grid = 2048 tiles (64 b x 32), 256 threads (8 warps).
// SMEM: act [128 x 264 bf16] (528B stride, conflict-free),
//       W chunks 2 x [256 x 136 bf16] (272B stride, conflict-free),
//       bias[256], acc[256].
// ============================================================================
static constexpr int ACT_STRIDE_B = 528;
static constexpr int ACT_STRIDE_H = 264;
static constexpr int WCH_STRIDE_B = 272;           // 128 K bf16 + 8 pad
static constexpr int SMEM_ACT  = 0;
static constexpr int SMEM_W0   = 128 * ACT_STRIDE_B;            // 67584
static constexpr int SMEM_W1   = SMEM_W0 + 256 * WCH_STRIDE_B;  // 137216
static constexpr int SMEM_BIAS = SMEM_W1 + 256 * WCH_STRIDE_B;  // 206848
static constexpr int SMEM_RACC = SMEM_BIAS + 1024;              // 207872
static constexpr int SMEM_MAIN_SZ = SMEM_RACC + 1024;           // 208896

__device__ __forceinline__ void stage_chunk_async(uint32_t smem_base, int buf_sel,
                                                  int L, int c, int tid) {
    const char* src = (const char*)g_Wbf + (size_t)(L * 2 + c) * 65536;
    uint32_t dstb = smem_base + (buf_sel ? SMEM_W1 : SMEM_W0);
#pragma unroll
    for (int i = 0; i < 16; i++) {
        int idx = i * 256 + tid;          // 16B unit index, 4096 total
        int row = idx >> 4;               // 16 x 16B per source row
        int col = idx & 15;
        CP_ASYNC16(dstb + row * WCH_STRIDE_B + col * 16, src + idx * 16);
    }
    CP_ASYNC_COMMIT();
}

__global__ void __launch_bounds__(256, 1)
k_main(const float* __restrict__ bg1, const float* __restrict__ bg2,
       const float* __restrict__ bg3, const float* __restrict__ bg4) {
    extern __shared__ char smem[];
    const uint32_t smem_base = smem_to_u32(smem);

    __nv_bfloat16* s_act = (__nv_bfloat16*)(smem + SMEM_ACT);
    float* s_bias = (float*)(smem + SMEM_BIAS);
    float* s_acc  = (float*)(smem + SMEM_RACC);

    int tid  = threadIdx.x;
    int wid  = tid >> 5;
    int lane = tid & 31;

    int b    = blockIdx.x >> 5;
    int row0 = (blockIdx.x & 31) << 7;

    s_acc[tid] = 0.0f;

    // prologue: prefetch layer-0 weight chunks while computing layer 1
    stage_chunk_async(smem_base, 0, 0, 0, tid);
    stage_chunk_async(smem_base, 1, 0, 1, tid);

    // ---- layer 1: act = relu(A[b,q] + C[b,p] + bg1), bf16 ----
    {
        int r = tid >> 1;
        int half = tid & 1;
        int rowg = row0 + r;
        int p = rowg >> 6, q = rowg & 63;
        const float2* A2 = (const float2*)(g_A + ((b << 6) + q) * HID + half * 128);
        const float2* C2 = (const float2*)(g_C + ((b << 6) + p) * HID + half * 128);
        const float2* B2 = (const float2*)(bg1 + half * 128);
        uint32_t* dst = (uint32_t*)(s_act + r * ACT_STRIDE_H + half * 128);
#pragma unroll
        for (int c = 0; c < 64; c++) {
            float2 av = A2[c], cv = C2[c], bv = B2[c];
            float f0 = fmaxf(av.x + cv.x + bv.x, 0.0f);
            float f1 = fmaxf(av.y + cv.y + bv.y, 0.0f);
            uint32_t lo = (uint32_t)__bfloat16_as_ushort(__float2bfloat16(f0));
            uint32_t hi = (uint32_t)__bfloat16_as_ushort(__float2bfloat16(f1));
            dst[c] = lo | (hi << 16);
        }
    }
    __syncthreads();

    // per-warp tile coordinates
    int warp_m = wid & 1;
    int warp_n = wid >> 1;
    int mbase = warp_m * 64;
    int nbase = warp_n * 64;

    uint32_t a_ptr[4];
#pragma unroll
    for (int mt = 0; mt < 4; mt++) {
        int rr = mbase + mt * 16 + (lane & 15);
        a_ptr[mt] = smem_base + SMEM_ACT + rr * ACT_STRIDE_B + (lane >> 4) * 16;
    }
    // weight-chunk fragment offsets (within a chunk buffer)
    uint32_t b_off[8];
#pragma unroll
    for (int nt = 0; nt < 8; nt++) {
        int rr = nbase + nt * 8 + (lane & 7);
        b_off[nt] = rr * WCH_STRIDE_B + ((lane >> 3) & 1) * 16;
    }

    // ---- layers 2..5 ----
#pragma unroll 1
    for (int L = 0; L < 4; L++) {
        const float* bp = (L == 0) ? bg2 : (L == 1) ? bg3 : (L == 2) ? bg4
                                         : (const float*)(g_qbias + b * 256);
        s_bias[tid] = bp[tid];

        float acc[4][8][4];
#pragma unroll
        for (int mt = 0; mt < 4; mt++)
#pragma unroll
            for (int nt = 0; nt < 8; nt++)
#pragma unroll
                for (int j = 0; j < 4; j++) acc[mt][nt][j] = 0.0f;

        // -- half 0: K 0..127 on buf0 --
        CP_ASYNC_WAIT(1);          // chunk0 of L landed
        __syncthreads();
        {
            uint32_t wb = smem_base + SMEM_W0;
#pragma unroll
            for (int ks = 0; ks < 8; ks++) {
                uint32_t af[4][4];
#pragma unroll
                for (int mt = 0; mt < 4; mt++)
                    LDSM_X4(af[mt][0], af[mt][1], af[mt][2], af[mt][3],
                            a_ptr[mt] + ks * 32);
                uint32_t bf[8][2];
#pragma unroll
                for (int nt = 0; nt < 8; nt++)
                    LDSM_X2(bf[nt][0], bf[nt][1], wb + b_off[nt] + ks * 32);
#pragma unroll
                for (int mt = 0; mt < 4; mt++)
#pragma unroll
                    for (int nt = 0; nt < 8; nt++)
                        MMA16816(acc[mt][nt][0], acc[mt][nt][1],
                                 acc[mt][nt][2], acc[mt][nt][3],
                                 af[mt][0], af[mt][1], af[mt][2], af[mt][3],
                                 bf[nt][0], bf[nt][1]);
            }
        }
        __syncthreads();           // everyone done reading buf0
        if (L < 3) stage_chunk_async(smem_base, 0, L + 1, 0, tid);

        // -- half 1: K 128..255 on buf1 --
        if (L < 3) CP_ASYNC_WAIT(1); else CP_ASYNC_WAIT(0);
        __syncthreads();
        {
            uint32_t wb = smem_base + SMEM_W1;
#pragma unroll
            for (int ks = 0; ks < 8; ks++) {
                uint32_t af[4][4];
#pragma unroll
                for (int mt = 0; mt < 4; mt++)
                    LDSM_X4(af[mt][0], af[mt][1], af[mt][2], af[mt][3],
                            a_ptr[mt] + 256 + ks * 32);
                uint32_t bf[8][2];
#pragma unroll
                for (int nt = 0; nt < 8; nt++)
                    LDSM_X2(bf[nt][0], bf[nt][1], wb + b_off[nt] + ks * 32);
#pragma unroll
                for (int mt = 0; mt < 4; mt++)
#pragma unroll
                    for (int nt = 0; nt < 8; nt++)
                        MMA16816(acc[mt][nt][0], acc[mt][nt][1],
                                 acc[mt][nt][2], acc[mt][nt][3],
                                 af[mt][0], af[mt][1], af[mt][2], af[mt][3],
                                 bf[nt][0], bf[nt][1]);
            }
        }
        __syncthreads();           // done reading buf1 AND act
        if (L < 3) stage_chunk_async(smem_base, 1, L + 1, 1, tid);

        if (L < 3) {
            // epilogue: act = bf16(relu(D + bias)), in place
#pragma unroll
            for (int mt = 0; mt < 4; mt++) {
                int r0 = mbase + mt * 16 + (lane >> 2);
#pragma unroll
                for (int nt = 0; nt < 8; nt++) {
                    int c0 = nbase + nt * 8 + (lane & 3) * 2;
                    float bia0 = s_bias[c0], bia1 = s_bias[c0 + 1];
                    float f0 = fmaxf(acc[mt][nt][0] + bia0, 0.0f);
                    float f1 = fmaxf(acc[mt][nt][1] + bia1, 0.0f);
                    float f2 = fmaxf(acc[mt][nt][2] + bia0, 0.0f);
                    float f3 = fmaxf(acc[mt][nt][3] + bia1, 0.0f);
                    uint32_t v01 = (uint32_t)__bfloat16_as_ushort(__float2bfloat16(f0))
                                 | ((uint32_t)__bfloat16_as_ushort(__float2bfloat16(f1)) << 16);
                    uint32_t v23 = (uint32_t)__bfloat16_as_ushort(__float2bfloat16(f2))
                                 | ((uint32_t)__bfloat16_as_ushort(__float2bfloat16(f3)) << 16);
                    *(uint32_t*)(s_act + r0 * ACT_STRIDE_H + c0) = v01;
                    *(uint32_t*)(s_act + (r0 + 8) * ACT_STRIDE_H + c0) = v23;
                }
            }
            __syncthreads();
        } else {
            // final layer: relu(D + qbias), sum over rows -> s_acc
#pragma unroll
            for (int nt = 0; nt < 8; nt++) {
                int c0 = nbase + nt * 8 + (lane & 3) * 2;
                float bia0 = s_bias[c0], bia1 = s_bias[c0 + 1];
                float cs0 = 0.0f, cs1 = 0.0f;
#pragma unroll
                for (int mt = 0; mt < 4; mt++) {
                    cs0 += fmaxf(acc[mt][nt][0] + bia0, 0.0f)
                         + fmaxf(acc[mt][nt][2] + bia0, 0.0f);
                    cs1 += fmaxf(acc[mt][nt][1] + bia1, 0.0f)
                         + fmaxf(acc[mt][nt][3] + bia1, 0.0f);
                }
#pragma unroll
                for (int s = 4; s < 32; s <<= 1) {
                    cs0 += __shfl_xor_sync(0xFFFFFFFF, cs0, s);
                    cs1 += __shfl_xor_sync(0xFFFFFFFF, cs1, s);
                }
                if ((lane >> 2) == 0) {
                    atomicAdd(&s_acc[c0], cs0);
                    atomicAdd(&s_acc[c0 + 1], cs1);
                }
            }
            __syncthreads();
        }
    }

    atomicAdd(&g_xg[b * 256 + tid], s_acc[tid]);
}

// ============================================================================
// K5: f-MLP + log_softmax (tiny). One block of 256 per batch.
// ============================================================================
__global__ void k_final(const float* __restrict__ Wf1, const float* __restrict__ bf1v,
                        const float* __restrict__ Wf2, const float* __restrict__ bf2v,
                        const float* __restrict__ Wf3, const float* __restrict__ bf3v,
                        float* __restrict__ out) {
    __shared__ float s0[256], s1[256], lg[NOUT];
    __shared__ float lse;
    int b = blockIdx.x, t = threadIdx.x;
    s0[t] = g_xg[b * 256 + t];
    __syncthreads();

    float a = bf1v[t];
    const float* w = Wf1 + t * 256;
#pragma unroll 8
    for (int i = 0; i < 256; i++) a += w[i] * s0[i];
    s1[t] = fmaxf(a, 0.0f);
    __syncthreads();

    a = bf2v[t];
    w = Wf2 + t * 256;
#pragma unroll 8
    for (int i = 0; i < 256; i++) a += w[i] * s1[i];
    s0[t] = fmaxf(a, 0.0f);
    __syncthreads();

    if (t < NOUT) {
        a = bf3v[t];
        w = Wf3 + t * 256;
#pragma unroll 8
        for (int i = 0; i < 256; i++) a += w[i] * s0[i];
        lg[t] = a;
    }
    __syncthreads();
    if (t == 0) {
        float m = lg[0];
        for (int i = 1; i < NOUT; i++) m = fmaxf(m, lg[i]);
        float se = 0.0f;
        for (int i = 0; i < NOUT; i++) se += expf(lg[i] - m);
        lse = m + logf(se);
    }
    __syncthreads();
    if (t < NOUT) out[b * NOUT + t] = lg[t] - lse;
}

// ============================================================================
// kernel_launch
// ============================================================================
extern "C" void kernel_launch(void* const* d_in, const int* in_sizes, int n_in,
                              void* d_out, int out_size) {
    const float* x    = (const float*)d_in[0];
    const float* qst  = (const float*)d_in[1];
    const float* Wg1  = (const float*)d_in[2];
    const float* bg1  = (const float*)d_in[3];
    const float* Wg2  = (const float*)d_in[4];
    const float* bg2  = (const float*)d_in[5];
    const float* Wg3  = (const float*)d_in[6];
    const float* bg3  = (const float*)d_in[7];
    const float* Wg4  = (const float*)d_in[8];
    const float* bg4  = (const float*)d_in[9];
    const float* Wh1  = (const float*)d_in[10];
    const float* bh1  = (const float*)d_in[11];
    const float* Wf1  = (const float*)d_in[12];
    const float* bf1v = (const float*)d_in[13];
    const float* Wf2  = (const float*)d_in[14];
    const float* bf2v = (const float*)d_in[15];
    const float* Wf3  = (const float*)d_in[16];
    const float* bf3v = (const float*)d_in[17];
    float* out = (float*)d_out;

    cudaFuncSetAttribute(k_main, cudaFuncAttributeMaxDynamicSharedMemorySize,
                         SMEM_MAIN_SZ);

    k_zero<<<NB, 256>>>();
    k_precompute_AC<<<NB, 256>>>(x, Wg1);
    k_qbias<<<NB, 256>>>(qst, Wh1, bh1);
    k_convw<<<1024, 256>>>(Wg2, Wg3, Wg4, Wh1);
    k_main<<<2048, 256, SMEM_MAIN_SZ>>>(bg1, bg2, bg3, bg4);
    k_final<<<NB, 256>>>(Wf1, bf1v, Wf2, bf2v, Wf3, bf3v, out);
}

// round 5
// speedup vs baseline: 1.0776x; 1.0619x over previous
#include <cuda_runtime.h>
#include <cuda_bf16.h>
#include <cstdint>

// ============================================================================
// Problem constants: B=64, K=24, D=8, n=64 obj, 4096 pairs/batch, IN=52
// ============================================================================
static constexpr int NB   = 64;
static constexpr int NOBJ = 64;
static constexpr int HID  = 256;
static constexpr int NOUT = 28;

// ============================================================================
// PTX helpers: ldmatrix + mma.sync + cp.async (sm_80-era, valid on sm_100)
// ============================================================================
__device__ __forceinline__ uint32_t smem_to_u32(const void* smem_ptr) {
    uint32_t addr;
    asm("{ .reg .u64 tmp; cvta.to.shared.u64 tmp, %1; cvt.u32.u64 %0, tmp; }"
        : "=r"(addr) : "l"(smem_ptr));
    return addr;
}

#define LDSM_X4(r0, r1, r2, r3, addr) \
    asm volatile("ldmatrix.sync.aligned.m8n8.x4.shared.b16 {%0,%1,%2,%3}, [%4];" \
                 : "=r"(r0), "=r"(r1), "=r"(r2), "=r"(r3) : "r"(addr))

#define LDSM_X2(r0, r1, addr) \
    asm volatile("ldmatrix.sync.aligned.m8n8.x2.shared.b16 {%0,%1}, [%2];" \
                 : "=r"(r0), "=r"(r1) : "r"(addr))

#define MMA16816(d0, d1, d2, d3, a0, a1, a2, a3, b0, b1) \
    asm volatile("mma.sync.aligned.m16n8k16.row.col.f32.bf16.bf16.f32 " \
                 "{%0,%1,%2,%3}, {%4,%5,%6,%7}, {%8,%9}, {%0,%1,%2,%3};" \
                 : "+f"(d0), "+f"(d1), "+f"(d2), "+f"(d3) \
                 : "r"(a0), "r"(a1), "r"(a2), "r"(a3), "r"(b0), "r"(b1))

#define CP_ASYNC16(dst_u32, src_ptr) \
    asm volatile("cp.async.cg.shared.global [%0], [%1], 16;" \
                 :: "r"(dst_u32), "l"(src_ptr))

#define CP_ASYNC_COMMIT() asm volatile("cp.async.commit_group;" ::: "memory")
#define CP_ASYNC_WAIT(n)  asm volatile("cp.async.wait_group %0;" :: "n"(n) : "memory")

// ============================================================================
// Device-global scratch (no dynamic allocation allowed)
// ============================================================================
__device__ __align__(16) float g_A[NB * NOBJ * HID];
__device__ __align__(16) float g_C[NB * NOBJ * HID];
__device__ __align__(16) float g_qbias[NB * HID];
__device__ float g_xg[NB * HID];
// chunked layout: [ci = layer*4 + kchunk][out 0..255][k 0..63] bf16
__device__ __align__(16) __nv_bfloat16 g_Wbf[4 * HID * HID];

// ============================================================================
// K1: A[b,q,o] = Wg1[o,:26].feat[b,q],  C[b,p,o] = Wg1[o,26:].feat[b,p]
// ============================================================================
__global__ void k_precompute_AC(const float* __restrict__ x,
                                const float* __restrict__ Wg1) {
    __shared__ float feat[NOBJ][26];
    int b = blockIdx.x;
    int t = threadIdx.x;   // 256

    for (int idx = t; idx < NOBJ * 26; idx += 256) {
        int j = idx / 26, i = idx % 26;
        int r = j >> 3, c = j & 7;
        float v;
        if (i < 24)       v = x[((b * 24 + i) * 8 + r) * 8 + c];
        else if (i == 24) v = c * (8.0f / 7.0f) - 4.0f;
        else              v = r * (8.0f / 7.0f) - 4.0f;
        feat[j][i] = v;
    }
    __syncthreads();

    int o = t;
    float wA[26], wC[26];
#pragma unroll
    for (int i = 0; i < 26; i++) {
        wA[i] = Wg1[o * 52 + i];
        wC[i] = Wg1[o * 52 + 26 + i];
    }
    for (int j = 0; j < NOBJ; j++) {
        float sa = 0.0f, sc = 0.0f;
#pragma unroll
        for (int i = 0; i < 26; i++) {
            float f = feat[j][i];
            sa += wA[i] * f;
            sc += wC[i] * f;
        }
        g_A[(b * NOBJ + j) * HID + o] = sa;
        g_C[(b * NOBJ + j) * HID + o] = sc;
    }
}

// ============================================================================
// K2: qbias[b,o] = bh1[o] + Wh1[o, 256:].qst[b]
// ============================================================================
__global__ void k_qbias(const float* __restrict__ qst,
                        const float* __restrict__ Wh1,
                        const float* __restrict__ bh1) {
    __shared__ float qs[256];
    int b = blockIdx.x, o = threadIdx.x;
    qs[o] = qst[b * 256 + o];
    __syncthreads();
    float s = bh1[o];
    const float* wr = Wh1 + o * 512 + 256;
#pragma unroll 8
    for (int i = 0; i < 256; i++) s += wr[i] * qs[i];
    g_qbias[b * 256 + o] = s;
}

// ============================================================================
// K3: weights fp32 -> bf16, chunk layout [L*4+c][out][k64]; also zeros g_xg
// ============================================================================
__global__ void k_convw(const float* __restrict__ Wg2, const float* __restrict__ Wg3,
                        const float* __restrict__ Wg4, const float* __restrict__ Wh1) {
    int idx = blockIdx.x * 256 + threadIdx.x;   // 0 .. 4*65536-1
    if (idx < NB * HID) g_xg[idx] = 0.0f;
    int layer = idx >> 16, e = idx & 65535;
    int o = e >> 8, i = e & 255;
    float v;
    if (layer == 0)      v = Wg2[e];
    else if (layer == 1) v = Wg3[e];
    else if (layer == 2) v = Wg4[e];
    else                 v = Wh1[o * 512 + i];
    int c = i >> 6, k = i & 63;
    g_Wbf[(((layer * 4 + c) * 256 + o) << 6) + k] = __float2bfloat16(v);
}

// ============================================================================
// K4: fused RN core, HMMA, 2 CTAs/SM.
// Grid = 4096 tiles (64 b x 64), 128 threads (4 warps), 64 pair-rows/CTA.
// SMEM: act [64 x 264 bf16] (528B stride), W chunks 2 x [256 x 72 bf16]
// (144B stride; 64 K data + pad — rows step 4 banks -> ldmatrix conflict-free),
// bias[256], acc[256]. Double-buffered cp.async over 16 global K-chunks.
// ============================================================================
static constexpr int ACT_STRIDE_B = 528;
static constexpr int ACT_STRIDE_H = 264;
static constexpr int WCH_STRIDE_B = 144;
static constexpr int SMEM_ACT  = 0;                             // 64*528 = 33792
static constexpr int SMEM_W0   = 33792;
static constexpr int SMEM_W1   = SMEM_W0 + 256 * WCH_STRIDE_B;  // 70656
static constexpr int SMEM_BIAS = SMEM_W1 + 256 * WCH_STRIDE_B;  // 107520
static constexpr int SMEM_RACC = SMEM_BIAS + 1024;              // 108544
static constexpr int SMEM_MAIN_SZ = SMEM_RACC + 1024;           // 109568

__device__ __forceinline__ void stage_chunk_async(uint32_t smem_base, int buf_sel,
                                                  int ci, int tid) {
    const char* src = (const char*)g_Wbf + (size_t)ci * 32768;
    uint32_t dstb = smem_base + (buf_sel ? SMEM_W1 : SMEM_W0);
#pragma unroll
    for (int i = 0; i < 16; i++) {
        int idx = i * 128 + tid;          // 16B unit, 2048 total
        int row = idx >> 3;               // 8 x 16B per 128B source row
        int col = idx & 7;
        CP_ASYNC16(dstb + row * WCH_STRIDE_B + col * 16, src + idx * 16);
    }
    CP_ASYNC_COMMIT();
}

__global__ void __launch_bounds__(128, 2)
k_main(const float* __restrict__ bg1, const float* __restrict__ bg2,
       const float* __restrict__ bg3, const float* __restrict__ bg4) {
    extern __shared__ char smem[];
    const uint32_t smem_base = smem_to_u32(smem);

    __nv_bfloat16* s_act = (__nv_bfloat16*)(smem + SMEM_ACT);
    float* s_bias = (float*)(smem + SMEM_BIAS);
    float* s_acc  = (float*)(smem + SMEM_RACC);

    int tid  = threadIdx.x;
    int wid  = tid >> 5;
    int lane = tid & 31;

    int b    = blockIdx.x >> 6;
    int row0 = (blockIdx.x & 63) << 6;   // 64 rows per CTA

    s_acc[tid] = 0.0f;
    s_acc[tid + 128] = 0.0f;

    // prologue: prefetch first two K-chunks of layer 0
    stage_chunk_async(smem_base, 0, 0, tid);
    stage_chunk_async(smem_base, 1, 1, tid);

    // ---- layer 1: act = relu(A[b,q] + C[b,p] + bg1), bf16, 64 rows ----
    {
        int r = tid >> 1;                 // 0..63
        int half = tid & 1;
        int rowg = row0 + r;
        int p = rowg >> 6, q = rowg & 63;
        const float2* A2 = (const float2*)(g_A + ((b << 6) + q) * HID + half * 128);
        const float2* C2 = (const float2*)(g_C + ((b << 6) + p) * HID + half * 128);
        const float2* B2 = (const float2*)(bg1 + half * 128);
        uint32_t* dst = (uint32_t*)(s_act + r * ACT_STRIDE_H + half * 128);
#pragma unroll
        for (int c = 0; c < 64; c++) {
            float2 av = A2[c], cv = C2[c], bv = B2[c];
            float f0 = fmaxf(av.x + cv.x + bv.x, 0.0f);
            float f1 = fmaxf(av.y + cv.y + bv.y, 0.0f);
            uint32_t lo = (uint32_t)__bfloat16_as_ushort(__float2bfloat16(f0));
            uint32_t hi = (uint32_t)__bfloat16_as_ushort(__float2bfloat16(f1));
            dst[c] = lo | (hi << 16);
        }
    }
    __syncthreads();

    // per-warp tile: all warps cover rows 0..63 (mt), 64-col slice by wid
    int nbase = wid * 64;

    uint32_t a_ptr[4];
#pragma unroll
    for (int mt = 0; mt < 4; mt++) {
        int rr = mt * 16 + (lane & 15);
        a_ptr[mt] = smem_base + SMEM_ACT + rr * ACT_STRIDE_B + (lane >> 4) * 16;
    }
    uint32_t b_off[8];
#pragma unroll
    for (int nt = 0; nt < 8; nt++) {
        int rr = nbase + nt * 8 + (lane & 7);
        b_off[nt] = rr * WCH_STRIDE_B + ((lane >> 3) & 1) * 16;
    }

    // ---- layers 2..5: 16 global K-chunks, double-buffered ----
    int ci = 0;
#pragma unroll 1
    for (int L = 0; L < 4; L++) {
        const float* bp = (L == 0) ? bg2 : (L == 1) ? bg3 : (L == 2) ? bg4
                                         : (const float*)(g_qbias + b * 256);
        s_bias[tid] = bp[tid];
        s_bias[tid + 128] = bp[tid + 128];

        float acc[4][8][4];
#pragma unroll
        for (int mt = 0; mt < 4; mt++)
#pragma unroll
            for (int nt = 0; nt < 8; nt++)
#pragma unroll
                for (int j = 0; j < 4; j++) acc[mt][nt][j] = 0.0f;

#pragma unroll 1
        for (int c = 0; c < 4; c++) {
            if (ci < 15) { CP_ASYNC_WAIT(1); } else { CP_ASYNC_WAIT(0); }
            __syncthreads();
            uint32_t wb = smem_base + ((ci & 1) ? SMEM_W1 : SMEM_W0);
#pragma unroll
            for (int ks = 0; ks < 4; ks++) {
                int kk = c * 4 + ks;      // global k-step within layer (0..15)
                uint32_t af[4][4];
#pragma unroll
                for (int mt = 0; mt < 4; mt++)
                    LDSM_X4(af[mt][0], af[mt][1], af[mt][2], af[mt][3],
                            a_ptr[mt] + kk * 32);
                uint32_t bf[8][2];
#pragma unroll
                for (int nt = 0; nt < 8; nt++)
                    LDSM_X2(bf[nt][0], bf[nt][1], wb + b_off[nt] + ks * 32);
#pragma unroll
                for (int mt = 0; mt < 4; mt++)
#pragma unroll
                    for (int nt = 0; nt < 8; nt++)
                        MMA16816(acc[mt][nt][0], acc[mt][nt][1],
                                 acc[mt][nt][2], acc[mt][nt][3],
                                 af[mt][0], af[mt][1], af[mt][2], af[mt][3],
                                 bf[nt][0], bf[nt][1]);
            }
            __syncthreads();              // all warps done reading this buffer
            if (ci + 2 < 16) stage_chunk_async(smem_base, ci & 1, ci + 2, tid);
            ci++;
        }

        if (L < 3) {
            // epilogue: act = bf16(relu(D + bias)), in place
#pragma unroll
            for (int mt = 0; mt < 4; mt++) {
                int r0 = mt * 16 + (lane >> 2);
#pragma unroll
                for (int nt = 0; nt < 8; nt++) {
                    int c0 = nbase + nt * 8 + (lane & 3) * 2;
                    float bia0 = s_bias[c0], bia1 = s_bias[c0 + 1];
                    float f0 = fmaxf(acc[mt][nt][0] + bia0, 0.0f);
                    float f1 = fmaxf(acc[mt][nt][1] + bia1, 0.0f);
                    float f2 = fmaxf(acc[mt][nt][2] + bia0, 0.0f);
                    float f3 = fmaxf(acc[mt][nt][3] + bia1, 0.0f);
                    uint32_t v01 = (uint32_t)__bfloat16_as_ushort(__float2bfloat16(f0))
                                 | ((uint32_t)__bfloat16_as_ushort(__float2bfloat16(f1)) << 16);
                    uint32_t v23 = (uint32_t)__bfloat16_as_ushort(__float2bfloat16(f2))
                                 | ((uint32_t)__bfloat16_as_ushort(__float2bfloat16(f3)) << 16);
                    *(uint32_t*)(s_act + r0 * ACT_STRIDE_H + c0) = v01;
                    *(uint32_t*)(s_act + (r0 + 8) * ACT_STRIDE_H + c0) = v23;
                }
            }
            __syncthreads();
        } else {
            // final layer: relu(D + qbias), sum over rows -> s_acc
#pragma unroll
            for (int nt = 0; nt < 8; nt++) {
                int c0 = nbase + nt * 8 + (lane & 3) * 2;
                float bia0 = s_bias[c0], bia1 = s_bias[c0 + 1];
                float cs0 = 0.0f, cs1 = 0.0f;
#pragma unroll
                for (int mt = 0; mt < 4; mt++) {
                    cs0 += fmaxf(acc[mt][nt][0] + bia0, 0.0f)
                         + fmaxf(acc[mt][nt][2] + bia0, 0.0f);
                    cs1 += fmaxf(acc[mt][nt][1] + bia1, 0.0f)
                         + fmaxf(acc[mt][nt][3] + bia1, 0.0f);
                }
#pragma unroll
                for (int s = 4; s < 32; s <<= 1) {
                    cs0 += __shfl_xor_sync(0xFFFFFFFF, cs0, s);
                    cs1 += __shfl_xor_sync(0xFFFFFFFF, cs1, s);
                }
                if ((lane >> 2) == 0) {
                    atomicAdd(&s_acc[c0], cs0);
                    atomicAdd(&s_acc[c0 + 1], cs1);
                }
            }
            __syncthreads();
        }
    }

    atomicAdd(&g_xg[b * 256 + tid], s_acc[tid]);
    atomicAdd(&g_xg[b * 256 + tid + 128], s_acc[tid + 128]);
}

// ============================================================================
// K5: f-MLP + log_softmax (tiny). One block of 256 per batch.
// ============================================================================
__global__ void k_final(const float* __restrict__ Wf1, const float* __restrict__ bf1v,
                        const float* __restrict__ Wf2, const float* __restrict__ bf2v,
                        const float* __restrict__ Wf3, const float* __restrict__ bf3v,
                        float* __restrict__ out) {
    __shared__ float s0[256], s1[256], lg[NOUT];
    __shared__ float lse;
    int b = blockIdx.x, t = threadIdx.x;
    s0[t] = g_xg[b * 256 + t];
    __syncthreads();

    float a = bf1v[t];
    const float* w = Wf1 + t * 256;
#pragma unroll 8
    for (int i = 0; i < 256; i++) a += w[i] * s0[i];
    s1[t] = fmaxf(a, 0.0f);
    __syncthreads();

    a = bf2v[t];
    w = Wf2 + t * 256;
#pragma unroll 8
    for (int i = 0; i < 256; i++) a += w[i] * s1[i];
    s0[t] = fmaxf(a, 0.0f);
    __syncthreads();

    if (t < NOUT) {
        a = bf3v[t];
        w = Wf3 + t * 256;
#pragma unroll 8
        for (int i = 0; i < 256; i++) a += w[i] * s0[i];
        lg[t] = a;
    }
    __syncthreads();
    if (t == 0) {
        float m = lg[0];
        for (int i = 1; i < NOUT; i++) m = fmaxf(m, lg[i]);
        float se = 0.0f;
        for (int i = 0; i < NOUT; i++) se += expf(lg[i] - m);
        lse = m + logf(se);
    }
    __syncthreads();
    if (t < NOUT) out[b * NOUT + t] = lg[t] - lse;
}

// ============================================================================
// kernel_launch — k_main placed 4th so ncu's captured slot lands on it
// ============================================================================
extern "C" void kernel_launch(void* const* d_in, const int* in_sizes, int n_in,
                              void* d_out, int out_size) {
    const float* x    = (const float*)d_in[0];
    const float* qst  = (const float*)d_in[1];
    const float* Wg1  = (const float*)d_in[2];
    const float* bg1  = (const float*)d_in[3];
    const float* Wg2  = (const float*)d_in[4];
    const float* bg2  = (const float*)d_in[5];
    const float* Wg3  = (const float*)d_in[6];
    const float* bg3  = (const float*)d_in[7];
    const float* Wg4  = (const float*)d_in[8];
    const float* bg4  = (const float*)d_in[9];
    const float* Wh1  = (const float*)d_in[10];
    const float* bh1  = (const float*)d_in[11];
    const float* Wf1  = (const float*)d_in[12];
    const float* bf1v = (const float*)d_in[13];
    const float* Wf2  = (const float*)d_in[14];
    const float* bf2v = (const float*)d_in[15];
    const float* Wf3  = (const float*)d_in[16];
    const float* bf3v = (const float*)d_in[17];
    float* out = (float*)d_out;

    cudaFuncSetAttribute(k_main, cudaFuncAttributeMaxDynamicSharedMemorySize,
                         SMEM_MAIN_SZ);

    k_precompute_AC<<<NB, 256>>>(x, Wg1);
    k_qbias<<<NB, 256>>>(qst, Wh1, bh1);
    k_convw<<<1024, 256>>>(Wg2, Wg3, Wg4, Wh1);   // also zeros g_xg
    k_main<<<4096, 128, SMEM_MAIN_SZ>>>(bg1, bg2, bg3, bg4);
    k_final<<<NB, 256>>>(Wf1, bf1v, Wf2, bf2v, Wf3, bf3v, out);
}

// round 6
// speedup vs baseline: 1.3405x; 1.2440x over previous
#include <cuda_runtime.h>
#include <cuda_bf16.h>
#include <cstdint>

// ============================================================================
// Problem constants: B=64, K=24, D=8, n=64 obj, 4096 pairs/batch, IN=52
// ============================================================================
static constexpr int NB   = 64;
static constexpr int NOBJ = 64;
static constexpr int HID  = 256;
static constexpr int NOUT = 28;

// ============================================================================
// PTX helpers: ldmatrix + mma.sync + cp.async (sm_80-era, valid on sm_100)
// ============================================================================
__device__ __forceinline__ uint32_t smem_to_u32(const void* smem_ptr) {
    uint32_t addr;
    asm("{ .reg .u64 tmp; cvta.to.shared.u64 tmp, %1; cvt.u32.u64 %0, tmp; }"
        : "=r"(addr) : "l"(smem_ptr));
    return addr;
}

#define LDSM_X4(r0, r1, r2, r3, addr) \
    asm volatile("ldmatrix.sync.aligned.m8n8.x4.shared.b16 {%0,%1,%2,%3}, [%4];" \
                 : "=r"(r0), "=r"(r1), "=r"(r2), "=r"(r3) : "r"(addr))

#define LDSM_X2(r0, r1, addr) \
    asm volatile("ldmatrix.sync.aligned.m8n8.x2.shared.b16 {%0,%1}, [%2];" \
                 : "=r"(r0), "=r"(r1) : "r"(addr))

#define MMA16816(d0, d1, d2, d3, a0, a1, a2, a3, b0, b1) \
    asm volatile("mma.sync.aligned.m16n8k16.row.col.f32.bf16.bf16.f32 " \
                 "{%0,%1,%2,%3}, {%4,%5,%6,%7}, {%8,%9}, {%0,%1,%2,%3};" \
                 : "+f"(d0), "+f"(d1), "+f"(d2), "+f"(d3) \
                 : "r"(a0), "r"(a1), "r"(a2), "r"(a3), "r"(b0), "r"(b1))

#define CP_ASYNC16(dst_u32, src_ptr) \
    asm volatile("cp.async.cg.shared.global [%0], [%1], 16;" \
                 :: "r"(dst_u32), "l"(src_ptr))

#define CP_ASYNC_COMMIT() asm volatile("cp.async.commit_group;" ::: "memory")
#define CP_ASYNC_WAIT(n)  asm volatile("cp.async.wait_group %0;" :: "n"(n) : "memory")

// ============================================================================
// Device-global scratch (no dynamic allocation allowed)
// ============================================================================
__device__ __align__(16) float g_A[NB * NOBJ * HID];
__device__ __align__(16) float g_C[NB * NOBJ * HID];
__device__ __align__(16) float g_qbias[NB * HID];
__device__ float g_xg[NB * HID];
// chunked layout: [ci = layer*4 + kchunk][out 0..255][k 0..63] bf16
__device__ __align__(16) __nv_bfloat16 g_Wbf[4 * HID * HID];

// ============================================================================
// K1: A[b,q,o] = Wg1[o,:26].feat[b,q],  C[b,p,o] = Wg1[o,26:].feat[b,p]
// grid = NB*4 (4 object-groups of 16 per batch) for better SM fill
// ============================================================================
__global__ void k_precompute_AC(const float* __restrict__ x,
                                const float* __restrict__ Wg1) {
    __shared__ float feat[16][26];
    int b  = blockIdx.x >> 2;
    int jg = blockIdx.x & 3;      // object group (16 objects)
    int t  = threadIdx.x;         // 256

    for (int idx = t; idx < 16 * 26; idx += 256) {
        int jj = idx / 26, i = idx % 26;
        int j = jg * 16 + jj;
        int r = j >> 3, c = j & 7;
        float v;
        if (i < 24)       v = x[((b * 24 + i) * 8 + r) * 8 + c];
        else if (i == 24) v = c * (8.0f / 7.0f) - 4.0f;
        else              v = r * (8.0f / 7.0f) - 4.0f;
        feat[jj][i] = v;
    }
    __syncthreads();

    int o = t;
    float wA[26], wC[26];
#pragma unroll
    for (int i = 0; i < 26; i++) {
        wA[i] = Wg1[o * 52 + i];
        wC[i] = Wg1[o * 52 + 26 + i];
    }
#pragma unroll
    for (int jj = 0; jj < 16; jj++) {
        float sa = 0.0f, sc = 0.0f;
#pragma unroll
        for (int i = 0; i < 26; i++) {
            float f = feat[jj][i];
            sa += wA[i] * f;
            sc += wC[i] * f;
        }
        int j = jg * 16 + jj;
        g_A[(b * NOBJ + j) * HID + o] = sa;
        g_C[(b * NOBJ + j) * HID + o] = sc;
    }
}

// ============================================================================
// K2: qbias[b,o] = bh1[o] + Wh1[o, 256:].qst[b] — warp-per-row, coalesced
// ============================================================================
__global__ void k_qbias(const float* __restrict__ qst,
                        const float* __restrict__ Wh1,
                        const float* __restrict__ bh1) {
    __shared__ float qs[256];
    int b = blockIdx.x, t = threadIdx.x;
    int w = t >> 5, lane = t & 31;
    qs[t] = qst[b * 256 + t];
    __syncthreads();
#pragma unroll 1
    for (int o = w; o < 256; o += 8) {
        const float* wr = Wh1 + o * 512 + 256;
        float s = 0.0f;
#pragma unroll
        for (int k = 0; k < 8; k++) s += wr[lane + 32 * k] * qs[lane + 32 * k];
#pragma unroll
        for (int sh = 16; sh; sh >>= 1) s += __shfl_xor_sync(0xFFFFFFFFu, s, sh);
        if (lane == 0) g_qbias[b * 256 + o] = s + bh1[o];
    }
}

// ============================================================================
// K3: weights fp32 -> bf16, chunk layout [L*4+c][out][k64]; also zeros g_xg
// ============================================================================
__global__ void k_convw(const float* __restrict__ Wg2, const float* __restrict__ Wg3,
                        const float* __restrict__ Wg4, const float* __restrict__ Wh1) {
    int idx = blockIdx.x * 256 + threadIdx.x;   // 0 .. 4*65536-1
    if (idx < NB * HID) g_xg[idx] = 0.0f;
    int layer = idx >> 16, e = idx & 65535;
    int o = e >> 8, i = e & 255;
    float v;
    if (layer == 0)      v = Wg2[e];
    else if (layer == 1) v = Wg3[e];
    else if (layer == 2) v = Wg4[e];
    else                 v = Wh1[o * 512 + i];
    int c = i >> 6, k = i & 63;
    g_Wbf[(((layer * 4 + c) * 256 + o) << 6) + k] = __float2bfloat16(v);
}

// ============================================================================
// K4: fused RN core, HMMA, 2 CTAs/SM, WARP-PRIVATE weight staging.
// Grid = 4096 tiles (64 b x 64), 128 threads (4 warps), 64 pair-rows/CTA.
// Each warp owns a 64-col slice of outputs -> it only reads rows
// [wid*64, wid*64+64) of each weight chunk. It stages those rows itself with
// its own cp.async groups and syncs with wait_group + __syncwarp — no block
// barriers inside the K loop. Block barriers only around the act epilogue.
// ============================================================================
static constexpr int ACT_STRIDE_B = 528;
static constexpr int ACT_STRIDE_H = 264;
static constexpr int WCH_STRIDE_B = 144;
static constexpr int SMEM_ACT  = 0;                             // 64*528 = 33792
static constexpr int SMEM_W0   = 33792;
static constexpr int SMEM_W1   = SMEM_W0 + 256 * WCH_STRIDE_B;  // 70656
static constexpr int SMEM_BIAS = SMEM_W1 + 256 * WCH_STRIDE_B;  // 107520
static constexpr int SMEM_RACC = SMEM_BIAS + 1024;              // 108544
static constexpr int SMEM_MAIN_SZ = SMEM_RACC + 1024;           // 109568

// Stage this warp's 64-row slice (8 KB) of global chunk ci into buffer buf_sel.
__device__ __forceinline__ void stage_slice_warp(uint32_t smem_base, int buf_sel,
                                                 int ci, int wid, int lane) {
    const char* src = (const char*)g_Wbf + (size_t)ci * 32768 + (size_t)wid * 8192;
    uint32_t dstb = smem_base + (buf_sel ? SMEM_W1 : SMEM_W0) + wid * 64 * WCH_STRIDE_B;
#pragma unroll
    for (int i = 0; i < 16; i++) {
        int idx = i * 32 + lane;          // 16B unit, 512 per warp slice
        int row = idx >> 3;               // 8 x 16B per 128B source row
        int col = idx & 7;
        CP_ASYNC16(dstb + row * WCH_STRIDE_B + col * 16, src + idx * 16);
    }
    CP_ASYNC_COMMIT();
}

__global__ void __launch_bounds__(128, 2)
k_main(const float* __restrict__ bg1, const float* __restrict__ bg2,
       const float* __restrict__ bg3, const float* __restrict__ bg4) {
    extern __shared__ char smem[];
    const uint32_t smem_base = smem_to_u32(smem);

    __nv_bfloat16* s_act = (__nv_bfloat16*)(smem + SMEM_ACT);
    float* s_bias = (float*)(smem + SMEM_BIAS);
    float* s_acc  = (float*)(smem + SMEM_RACC);

    int tid  = threadIdx.x;
    int wid  = tid >> 5;
    int lane = tid & 31;

    int b    = blockIdx.x >> 6;
    int row0 = (blockIdx.x & 63) << 6;   // 64 rows per CTA

    s_acc[tid] = 0.0f;
    s_acc[tid + 128] = 0.0f;

    // prologue: each warp prefetches its slice of chunks 0 and 1
    stage_slice_warp(smem_base, 0, 0, wid, lane);
    stage_slice_warp(smem_base, 1, 1, wid, lane);

    // ---- layer 1: act = relu(A[b,q] + C[b,p] + bg1), bf16, 64 rows ----
    {
        int r = tid >> 1;                 // 0..63
        int half = tid & 1;
        int rowg = row0 + r;
        int p = rowg >> 6, q = rowg & 63;
        const float2* A2 = (const float2*)(g_A + ((b << 6) + q) * HID + half * 128);
        const float2* C2 = (const float2*)(g_C + ((b << 6) + p) * HID + half * 128);
        const float2* B2 = (const float2*)(bg1 + half * 128);
        uint32_t* dst = (uint32_t*)(s_act + r * ACT_STRIDE_H + half * 128);
#pragma unroll
        for (int c = 0; c < 64; c++) {
            float2 av = A2[c], cv = C2[c], bv = B2[c];
            float f0 = fmaxf(av.x + cv.x + bv.x, 0.0f);
            float f1 = fmaxf(av.y + cv.y + bv.y, 0.0f);
            uint32_t lo = (uint32_t)__bfloat16_as_ushort(__float2bfloat16(f0));
            uint32_t hi = (uint32_t)__bfloat16_as_ushort(__float2bfloat16(f1));
            dst[c] = lo | (hi << 16);
        }
    }
    __syncthreads();

    // per-warp tile: all warps cover rows 0..63 (mt), 64-col slice by wid
    int nbase = wid * 64;

    uint32_t a_ptr[4];
#pragma unroll
    for (int mt = 0; mt < 4; mt++) {
        int rr = mt * 16 + (lane & 15);
        a_ptr[mt] = smem_base + SMEM_ACT + rr * ACT_STRIDE_B + (lane >> 4) * 16;
    }
    uint32_t b_off[8];
#pragma unroll
    for (int nt = 0; nt < 8; nt++) {
        int rr = nbase + nt * 8 + (lane & 7);
        b_off[nt] = rr * WCH_STRIDE_B + ((lane >> 3) & 1) * 16;
    }

    // ---- layers 2..5: 16 global K-chunks, warp-private double buffering ----
    int ci = 0;
#pragma unroll 1
    for (int L = 0; L < 4; L++) {
        const float* bp = (L == 0) ? bg2 : (L == 1) ? bg3 : (L == 2) ? bg4
                                         : (const float*)(g_qbias + b * 256);
        s_bias[tid] = bp[tid];
        s_bias[tid + 128] = bp[tid + 128];

        float acc[4][8][4];
#pragma unroll
        for (int mt = 0; mt < 4; mt++)
#pragma unroll
            for (int nt = 0; nt < 8; nt++)
#pragma unroll
                for (int j = 0; j < 4; j++) acc[mt][nt][j] = 0.0f;

#pragma unroll 1
        for (int c = 0; c < 4; c++) {
            if (ci < 15) { CP_ASYNC_WAIT(1); } else { CP_ASYNC_WAIT(0); }
            __syncwarp();
            uint32_t wb = smem_base + ((ci & 1) ? SMEM_W1 : SMEM_W0);
#pragma unroll
            for (int ks = 0; ks < 4; ks++) {
                int kk = c * 4 + ks;      // global k-step within layer (0..15)
                uint32_t af[4][4];
#pragma unroll
                for (int mt = 0; mt < 4; mt++)
                    LDSM_X4(af[mt][0], af[mt][1], af[mt][2], af[mt][3],
                            a_ptr[mt] + kk * 32);
                uint32_t bf[8][2];
#pragma unroll
                for (int nt = 0; nt < 8; nt++)
                    LDSM_X2(bf[nt][0], bf[nt][1], wb + b_off[nt] + ks * 32);
#pragma unroll
                for (int mt = 0; mt < 4; mt++)
#pragma unroll
                    for (int nt = 0; nt < 8; nt++)
                        MMA16816(acc[mt][nt][0], acc[mt][nt][1],
                                 acc[mt][nt][2], acc[mt][nt][3],
                                 af[mt][0], af[mt][1], af[mt][2], af[mt][3],
                                 bf[nt][0], bf[nt][1]);
            }
            // this warp done reading its slice of this buffer — restage it
            if (ci + 2 < 16) stage_slice_warp(smem_base, ci & 1, ci + 2, wid, lane);
            ci++;
        }

        if (L < 3) {
            __syncthreads();   // all warps done reading act for this layer
            // epilogue: act = bf16(relu(D + bias)), in place
#pragma unroll
            for (int mt = 0; mt < 4; mt++) {
                int r0 = mt * 16 + (lane >> 2);
#pragma unroll
                for (int nt = 0; nt < 8; nt++) {
                    int c0 = nbase + nt * 8 + (lane & 3) * 2;
                    float bia0 = s_bias[c0], bia1 = s_bias[c0 + 1];
                    float f0 = fmaxf(acc[mt][nt][0] + bia0, 0.0f);
                    float f1 = fmaxf(acc[mt][nt][1] + bia1, 0.0f);
                    float f2 = fmaxf(acc[mt][nt][2] + bia0, 0.0f);
                    float f3 = fmaxf(acc[mt][nt][3] + bia1, 0.0f);
                    uint32_t v01 = (uint32_t)__bfloat16_as_ushort(__float2bfloat16(f0))
                                 | ((uint32_t)__bfloat16_as_ushort(__float2bfloat16(f1)) << 16);
                    uint32_t v23 = (uint32_t)__bfloat16_as_ushort(__float2bfloat16(f2))
                                 | ((uint32_t)__bfloat16_as_ushort(__float2bfloat16(f3)) << 16);
                    *(uint32_t*)(s_act + r0 * ACT_STRIDE_H + c0) = v01;
                    *(uint32_t*)(s_act + (r0 + 8) * ACT_STRIDE_H + c0) = v23;
                }
            }
            __syncthreads();
        } else {
            // final layer: relu(D + qbias), sum over rows -> s_acc
#pragma unroll
            for (int nt = 0; nt < 8; nt++) {
                int c0 = nbase + nt * 8 + (lane & 3) * 2;
                float bia0 = s_bias[c0], bia1 = s_bias[c0 + 1];
                float cs0 = 0.0f, cs1 = 0.0f;
#pragma unroll
                for (int mt = 0; mt < 4; mt++) {
                    cs0 += fmaxf(acc[mt][nt][0] + bia0, 0.0f)
                         + fmaxf(acc[mt][nt][2] + bia0, 0.0f);
                    cs1 += fmaxf(acc[mt][nt][1] + bia1, 0.0f)
                         + fmaxf(acc[mt][nt][3] + bia1, 0.0f);
                }
#pragma unroll
                for (int s = 4; s < 32; s <<= 1) {
                    cs0 += __shfl_xor_sync(0xFFFFFFFF, cs0, s);
                    cs1 += __shfl_xor_sync(0xFFFFFFFF, cs1, s);
                }
                if ((lane >> 2) == 0) {
                    atomicAdd(&s_acc[c0], cs0);
                    atomicAdd(&s_acc[c0 + 1], cs1);
                }
            }
            __syncthreads();
        }
    }

    atomicAdd(&g_xg[b * 256 + tid], s_acc[tid]);
    atomicAdd(&g_xg[b * 256 + tid + 128], s_acc[tid + 128]);
}

// ============================================================================
// K5: f-MLP + log_softmax — warp-per-row coalesced matvecs
// ============================================================================
__global__ void k_final(const float* __restrict__ Wf1, const float* __restrict__ bf1v,
                        const float* __restrict__ Wf2, const float* __restrict__ bf2v,
                        const float* __restrict__ Wf3, const float* __restrict__ bf3v,
                        float* __restrict__ out) {
    __shared__ float s0[256], s1[256], lg[NOUT];
    __shared__ float lse;
    int b = blockIdx.x, t = threadIdx.x;
    int w = t >> 5, lane = t & 31;
    s0[t] = g_xg[b * 256 + t];
    __syncthreads();

#pragma unroll 1
    for (int o = w; o < 256; o += 8) {
        const float* wr = Wf1 + o * 256;
        float s = 0.0f;
#pragma unroll
        for (int k = 0; k < 8; k++) s += wr[lane + 32 * k] * s0[lane + 32 * k];
#pragma unroll
        for (int sh = 16; sh; sh >>= 1) s += __shfl_xor_sync(0xFFFFFFFFu, s, sh);
        if (lane == 0) s1[o] = fmaxf(s + bf1v[o], 0.0f);
    }
    __syncthreads();

#pragma unroll 1
    for (int o = w; o < 256; o += 8) {
        const float* wr = Wf2 + o * 256;
        float s = 0.0f;
#pragma unroll
        for (int k = 0; k < 8; k++) s += wr[lane + 32 * k] * s1[lane + 32 * k];
#pragma unroll
        for (int sh = 16; sh; sh >>= 1) s += __shfl_xor_sync(0xFFFFFFFFu, s, sh);
        if (lane == 0) s0[o] = fmaxf(s + bf2v[o], 0.0f);
    }
    __syncthreads();

#pragma unroll 1
    for (int o = w; o < NOUT; o += 8) {
        const float* wr = Wf3 + o * 256;
        float s = 0.0f;
#pragma unroll
        for (int k = 0; k < 8; k++) s += wr[lane + 32 * k] * s0[lane + 32 * k];
#pragma unroll
        for (int sh = 16; sh; sh >>= 1) s += __shfl_xor_sync(0xFFFFFFFFu, s, sh);
        if (lane == 0) lg[o] = s + bf3v[o];
    }
    __syncthreads();
    if (t == 0) {
        float m = lg[0];
        for (int i = 1; i < NOUT; i++) m = fmaxf(m, lg[i]);
        float se = 0.0f;
        for (int i = 0; i < NOUT; i++) se += expf(lg[i] - m);
        lse = m + logf(se);
    }
    __syncthreads();
    if (t < NOUT) out[b * NOUT + t] = lg[t] - lse;
}

// ============================================================================
// kernel_launch — k_main 4th so ncu's captured slot lands on it
// ============================================================================
extern "C" void kernel_launch(void* const* d_in, const int* in_sizes, int n_in,
                              void* d_out, int out_size) {
    const float* x    = (const float*)d_in[0];
    const float* qst  = (const float*)d_in[1];
    const float* Wg1  = (const float*)d_in[2];
    const float* bg1  = (const float*)d_in[3];
    const float* Wg2  = (const float*)d_in[4];
    const float* bg2  = (const float*)d_in[5];
    const float* Wg3  = (const float*)d_in[6];
    const float* bg3  = (const float*)d_in[7];
    const float* Wg4  = (const float*)d_in[8];
    const float* bg4  = (const float*)d_in[9];
    const float* Wh1  = (const float*)d_in[10];
    const float* bh1  = (const float*)d_in[11];
    const float* Wf1  = (const float*)d_in[12];
    const float* bf1v = (const float*)d_in[13];
    const float* Wf2  = (const float*)d_in[14];
    const float* bf2v = (const float*)d_in[15];
    const float* Wf3  = (const float*)d_in[16];
    const float* bf3v = (const float*)d_in[17];
    float* out = (float*)d_out;

    cudaFuncSetAttribute(k_main, cudaFuncAttributeMaxDynamicSharedMemorySize,
                         SMEM_MAIN_SZ);

    k_precompute_AC<<<NB * 4, 256>>>(x, Wg1);
    k_qbias<<<NB, 256>>>(qst, Wh1, bh1);
    k_convw<<<1024, 256>>>(Wg2, Wg3, Wg4, Wh1);   // also zeros g_xg
    k_main<<<4096, 128, SMEM_MAIN_SZ>>>(bg1, bg2, bg3, bg4);
    k_final<<<NB, 256>>>(Wf1, bf1v, Wf2, bf2v, Wf3, bf3v, out);
}